// round 10
// baseline (speedup 1.0000x reference)
#include <cuda_runtime.h>
#include <cuda_bf16.h>
#include <cstdint>

#define S_LEN 8192
#define HID   2048
#define DIN   2048

#define NCTA  128
#define ROWS_PER_CTA 16   // 2048 / 128
#define SCAN_TPB 512

#define SENT 0x7fbfffffu   // NaN bit pattern: tanh output can never equal this

// ---------------- device scratch (no allocation allowed) ----------------
// Referenced ONLY from device code (never passed as a kernel arg from host).
__device__ float     g_xp[(size_t)S_LEN * HID];   // 64 MB input projection
__device__ float     g_hr[4][HID];                // 4-deep hidden-state ring

// packed fp32x2 FMA (sm_100+ FFMA2 path — only reachable via PTX)
__device__ __forceinline__ unsigned long long fma_f32x2(
    unsigned long long a, unsigned long long b, unsigned long long c) {
    unsigned long long d;
    asm("fma.rn.f32x2 %0, %1, %2, %3;" : "=l"(d) : "l"(a), "l"(b), "l"(c));
    return d;
}
__device__ __forceinline__ unsigned long long pack_f32x2(float lo, float hi) {
    unsigned long long d;
    asm("mov.b64 %0, {%1, %2};" : "=l"(d) : "f"(lo), "f"(hi));
    return d;
}
__device__ __forceinline__ void unpack_f32x2(unsigned long long v, float& lo, float& hi) {
    asm("mov.b64 {%0, %1}, %2;" : "=f"(lo), "=f"(hi) : "l"(v));
}

__device__ __forceinline__ uint4 ld_vol4(const uint4* p) {
    uint4 v;
    asm volatile("ld.volatile.global.v4.u32 {%0,%1,%2,%3}, [%4];"
                 : "=r"(v.x), "=r"(v.y), "=r"(v.z), "=r"(v.w) : "l"(p) : "memory");
    return v;
}
__device__ __forceinline__ void st_vol_f32(float* p, float v) {
    asm volatile("st.volatile.global.f32 [%0], %1;" :: "l"(p), "f"(v) : "memory");
}
__device__ __forceinline__ void st_vol_u32(unsigned* p, unsigned v) {
    asm volatile("st.volatile.global.u32 [%0], %1;" :: "l"(p), "r"(v) : "memory");
}

// ---------------- x_proj GEMM: g_xp = X @ Wi^T + bi (+ ring init) ----------------
#define BM 128
#define BN 128
#define BK 16

__global__ __launch_bounds__(256, 2) void gemm_xproj(
    const float* __restrict__ X,
    const float* __restrict__ Wi,
    const float* __restrict__ bi)
{
    // block (0,0) resets the h ring: slot 0 = h_0 = 0, slots 1..3 = sentinel.
    // (scan_kernel launches after this kernel completes — stream order.)
    if (blockIdx.x == 0 && blockIdx.y == 0) {
        for (int i = threadIdx.x; i < 4 * HID; i += 256)
            ((unsigned*)g_hr)[i] = (i < HID) ? 0u : SENT;
    }

    __shared__ float As[BK][BM + 4];
    __shared__ float Bs[BK][BN + 4];

    const int m0 = blockIdx.y * BM;
    const int n0 = blockIdx.x * BN;
    const int tid = threadIdx.x;
    const int tx = tid & 15;
    const int ty = tid >> 4;

    const int lrow = tid >> 2;
    const int lk   = (tid & 3) * 4;

    const float* Ag = X  + (size_t)m0 * DIN;
    const float* Bg = Wi + (size_t)n0 * DIN;

    typedef unsigned long long ull;
    union F4U { float4 f; ull u[2]; };

    ull acc2[4][8];   // a-pair (i/2) x j
#pragma unroll
    for (int ip = 0; ip < 4; ip++)
#pragma unroll
        for (int j = 0; j < 8; j++) acc2[ip][j] = 0ull;

    for (int kk = 0; kk < DIN; kk += BK) {
#pragma unroll
        for (int q = 0; q < 2; q++) {
            int r = lrow + 64 * q;
            float4 va = *(const float4*)&Ag[(size_t)r * DIN + kk + lk];
            As[lk + 0][r] = va.x; As[lk + 1][r] = va.y;
            As[lk + 2][r] = va.z; As[lk + 3][r] = va.w;
            float4 vb = *(const float4*)&Bg[(size_t)r * DIN + kk + lk];
            Bs[lk + 0][r] = vb.x; Bs[lk + 1][r] = vb.y;
            Bs[lk + 2][r] = vb.z; Bs[lk + 3][r] = vb.w;
        }
        __syncthreads();

#pragma unroll
        for (int k = 0; k < BK; k++) {
            F4U a0, a1;   // a-pairs come free from the vector load
            a0.f = *(const float4*)&As[k][ty * 8];
            a1.f = *(const float4*)&As[k][ty * 8 + 4];
            ull ap[4] = { a0.u[0], a0.u[1], a1.u[0], a1.u[1] };
            float b[8];
            *(float4*)&b[0] = *(const float4*)&Bs[k][tx * 8];
            *(float4*)&b[4] = *(const float4*)&Bs[k][tx * 8 + 4];
#pragma unroll
            for (int j = 0; j < 8; j++) {
                ull bb = pack_f32x2(b[j], b[j]);
#pragma unroll
                for (int ip = 0; ip < 4; ip++)
                    acc2[ip][j] = fma_f32x2(ap[ip], bb, acc2[ip][j]);
            }
        }
        __syncthreads();
    }

    // epilogue: unpack, add bias, store
#pragma unroll
    for (int ip = 0; ip < 4; ip++) {
        float row0v[8], row1v[8];
#pragma unroll
        for (int j = 0; j < 8; j++) unpack_f32x2(acc2[ip][j], row0v[j], row1v[j]);
        int m_a = m0 + ty * 8 + 2 * ip;
        int m_b = m_a + 1;
#pragma unroll
        for (int j = 0; j < 8; j += 4) {
            int n = n0 + tx * 8 + j;
            float4 v;
            v.x = row0v[j + 0] + bi[n + 0];
            v.y = row0v[j + 1] + bi[n + 1];
            v.z = row0v[j + 2] + bi[n + 2];
            v.w = row0v[j + 3] + bi[n + 3];
            *(float4*)&g_xp[(size_t)m_a * HID + n] = v;
            float4 u;
            u.x = row1v[j + 0] + bi[n + 0];
            u.y = row1v[j + 1] + bi[n + 1];
            u.z = row1v[j + 2] + bi[n + 2];
            u.w = row1v[j + 3] + bi[n + 3];
            *(float4*)&g_xp[(size_t)m_b * HID + n] = u;
        }
    }
}

// ---------------- persistent scan kernel, barrier-free (data-as-flag) ----------------
// 128 CTAs x 512 threads, Wh register-resident (64 fp32 / thread, packed f32x2).
// h is loaded DIRECTLY from L2 with per-chunk sentinel spins (no SMEM staging):
// in-warp dedup makes the L2 cost identical to a cooperative gather, and each
// thread starts FMA on early-arriving chunks while late chunks are in flight.
// Synchronization within a CTA: plain __syncthreads + double-buffered red[t&1]
// (skew inside a CTA is <= 1 step). Warp 0 does the tail and the h-store,
// which IS the cross-CTA release. Slot map at step t: read t&3, write (t+1)&3,
// sentinel-reset (t+3)&3 (own rows, post-sync: h_t fully observed => every CTA
// finished reading h_{t-1} => that slot is dead).
__global__ __launch_bounds__(SCAN_TPB, 1) void scan_kernel(
    const float* __restrict__ Wh,
    const float* __restrict__ bh,
    float* __restrict__ out,
    int write_tail)
{
    const int bid  = blockIdx.x;
    const int tid  = threadIdx.x;
    const int w    = tid >> 5;
    const int lane = tid & 31;
    const int kg_lo = lane & 7;
    const int rg    = lane >> 3;
    const int kg    = w * 8 + kg_lo;
    const int row0  = bid * ROWS_PER_CTA + rg * 4;

    typedef unsigned long long ull;
    union Pk { float4 f; uint4 i; ull u[2]; };

    // preload weights, packed as f32x2
    ull Wp[4][8];
#pragma unroll
    for (int r = 0; r < 4; r++)
#pragma unroll
        for (int i = 0; i < 4; i++) {
            Pk v;
            v.f = *(const float4*)&Wh[(size_t)(row0 + r) * HID + kg * 4 + i * 512];
            Wp[r][2 * i]     = v.u[0];
            Wp[r][2 * i + 1] = v.u[1];
        }

    __shared__ float red[2][ROWS_PER_CTA][20];   // double-buffered partials

    // warp-0 tail state: lane L handles row L>>1 (duplicated across lane pairs)
    const int trow = lane >> 1;
    const float bhv = bh[bid * ROWS_PER_CTA + trow];
    const float* xp_base = &g_xp[bid * ROWS_PER_CTA + trow];
    float x0 = 0.f, x1 = 0.f, x2 = 0.f, x3 = 0.f;
    if (w == 0) {
        x0 = __ldcs(&xp_base[(size_t)0 * HID]);
        x1 = __ldcs(&xp_base[(size_t)1 * HID]);
        x2 = __ldcs(&xp_base[(size_t)2 * HID]);
        x3 = __ldcs(&xp_base[(size_t)3 * HID]);
    }

    for (int t = 0; t < S_LEN; t++) {
        const uint4* hsrc = (const uint4*)g_hr[t & 3];

        float xpv = 0.f;
        if (w == 0) {   // rotate xp ring, prefetch t+4
            xpv = x0; x0 = x1; x1 = x2; x2 = x3;
            int tp = t + 4 < S_LEN ? t + 4 : S_LEN - 1;
            x3 = __ldcs(&xp_base[(size_t)tp * HID]);
        }

        // issue all 4 chunk loads (MLP), then per-chunk spin + FMA overlap
        Pk hv[4];
#pragma unroll
        for (int i = 0; i < 4; i++) hv[i].i = ld_vol4(hsrc + kg + i * 128);

        ull a2[4] = {0ull, 0ull, 0ull, 0ull};
#pragma unroll
        for (int i = 0; i < 4; i++) {
            while (hv[i].i.x == SENT || hv[i].i.y == SENT ||
                   hv[i].i.z == SENT || hv[i].i.w == SENT)
                hv[i].i = ld_vol4(hsrc + kg + i * 128);
#pragma unroll
            for (int r = 0; r < 4; r++) {
                a2[r] = fma_f32x2(Wp[r][2 * i],     hv[i].u[0], a2[r]);
                a2[r] = fma_f32x2(Wp[r][2 * i + 1], hv[i].u[1], a2[r]);
            }
        }

        float acc[4];
#pragma unroll
        for (int r = 0; r < 4; r++) {
            float lo, hi;
            unpack_f32x2(a2[r], lo, hi);
            acc[r] = lo + hi;
        }

        // reduce across the 8 kg_lo lanes within each rg group
#pragma unroll
        for (int d = 1; d < 8; d <<= 1) {
            acc[0] += __shfl_xor_sync(0xffffffffu, acc[0], d);
            acc[1] += __shfl_xor_sync(0xffffffffu, acc[1], d);
            acc[2] += __shfl_xor_sync(0xffffffffu, acc[2], d);
            acc[3] += __shfl_xor_sync(0xffffffffu, acc[3], d);
        }
        if (kg_lo == 0) {
            red[t & 1][rg * 4 + 0][w] = acc[0];
            red[t & 1][rg * 4 + 1][w] = acc[1];
            red[t & 1][rg * 4 + 2][w] = acc[2];
            red[t & 1][rg * 4 + 3][w] = acc[3];
        }
        __syncthreads();   // red complete; also: h_t fully observed by this CTA

        if (w == 0) {
            // tail: lane L -> row L>>1, half L&1
            const int half = lane & 1;
            float4 p0 = *(const float4*)&red[t & 1][trow][half * 8];
            float4 p1 = *(const float4*)&red[t & 1][trow][half * 8 + 4];
            float s = ((p0.x + p0.y) + (p0.z + p0.w))
                    + ((p1.x + p1.y) + (p1.z + p1.w));
            s += __shfl_xor_sync(0xffffffffu, s, 1);   // full row sum at even lanes
            float v = tanhf(s + bhv + xpv);
            float v16 = __shfl_sync(0xffffffffu, v, 2 * (lane & 15));
            if (lane < ROWS_PER_CTA) {
                int j = bid * ROWS_PER_CTA + lane;
                st_vol_f32(&g_hr[(t + 1) & 3][j], v16);  // release: data IS the flag
                __stcs(&out[(size_t)t * HID + j], v16);
                if (write_tail && t == S_LEN - 1)
                    out[(size_t)S_LEN * HID + j] = v16;  // final hidden state h_n
                // sentinel-reset own rows of the dead slot (h_{t-1}'s slot)
                st_vol_u32((unsigned*)&g_hr[(t + 3) & 3][j], SENT);
            }
        }
        // producer warps proceed straight into step t+1's polls (blocked until
        // every CTA's warp 0 has released h_{t+1}); red is double-buffered.
    }
}

// ---------------- launch ----------------
extern "C" void kernel_launch(void* const* d_in, const int* in_sizes, int n_in,
                              void* d_out, int out_size) {
    const float* x  = (const float*)d_in[0];
    const float* Wi = (const float*)d_in[1];
    const float* bi = (const float*)d_in[2];
    const float* Wh = (const float*)d_in[3];
    const float* bh = (const float*)d_in[4];
    float* out = (float*)d_out;

    gemm_xproj<<<dim3(HID / BN, S_LEN / BM), 256>>>(x, Wi, bi);

    int write_tail = (out_size >= S_LEN * HID + HID) ? 1 : 0;
    scan_kernel<<<NCTA, SCAN_TPB>>>(Wh, bh, out, write_tail);
}

// round 11
// speedup vs baseline: 1.0062x; 1.0062x over previous
#include <cuda_runtime.h>
#include <cuda_bf16.h>
#include <cstdint>

#define S_LEN 8192
#define HID   2048
#define DIN   2048

#define NCTA  128
#define ROWS_PER_CTA 16   // 2048 / 128
#define SCAN_TPB 512

#define SENT 0x7fbfffffu   // NaN bit pattern: tanh output can never equal this

// ---------------- device scratch (no allocation allowed) ----------------
// Referenced ONLY from device code (never passed as a kernel arg from host).
__device__ float     g_xp[(size_t)S_LEN * HID];   // 64 MB input projection
__device__ float     g_hr[4][HID];                // 4-deep hidden-state ring

// packed fp32x2 FMA (sm_100+ FFMA2 path — only reachable via PTX)
__device__ __forceinline__ unsigned long long fma_f32x2(
    unsigned long long a, unsigned long long b, unsigned long long c) {
    unsigned long long d;
    asm("fma.rn.f32x2 %0, %1, %2, %3;" : "=l"(d) : "l"(a), "l"(b), "l"(c));
    return d;
}
__device__ __forceinline__ unsigned long long pack_f32x2(float lo, float hi) {
    unsigned long long d;
    asm("mov.b64 %0, {%1, %2};" : "=l"(d) : "f"(lo), "f"(hi));
    return d;
}
__device__ __forceinline__ void unpack_f32x2(unsigned long long v, float& lo, float& hi) {
    asm("mov.b64 {%0, %1}, %2;" : "=f"(lo), "=f"(hi) : "l"(v));
}

__device__ __forceinline__ uint4 ld_vol4(const uint4* p) {
    uint4 v;
    asm volatile("ld.volatile.global.v4.u32 {%0,%1,%2,%3}, [%4];"
                 : "=r"(v.x), "=r"(v.y), "=r"(v.z), "=r"(v.w) : "l"(p) : "memory");
    return v;
}
__device__ __forceinline__ void st_vol_f32(float* p, float v) {
    asm volatile("st.volatile.global.f32 [%0], %1;" :: "l"(p), "f"(v) : "memory");
}
__device__ __forceinline__ void st_vol_u32(unsigned* p, unsigned v) {
    asm volatile("st.volatile.global.u32 [%0], %1;" :: "l"(p), "r"(v) : "memory");
}

// ---------------- x_proj GEMM: g_xp = X @ Wi^T + bi (+ ring init) ----------------
#define BM 128
#define BN 128
#define BK 16

__global__ __launch_bounds__(256, 2) void gemm_xproj(
    const float* __restrict__ X,
    const float* __restrict__ Wi,
    const float* __restrict__ bi)
{
    // block (0,0) resets the h ring: slot 0 = h_0 = 0, slots 1..3 = sentinel.
    // (scan_kernel launches after this kernel completes — stream order.)
    if (blockIdx.x == 0 && blockIdx.y == 0) {
        for (int i = threadIdx.x; i < 4 * HID; i += 256)
            ((unsigned*)g_hr)[i] = (i < HID) ? 0u : SENT;
    }

    __shared__ float As[BK][BM + 4];
    __shared__ float Bs[BK][BN + 4];

    const int m0 = blockIdx.y * BM;
    const int n0 = blockIdx.x * BN;
    const int tid = threadIdx.x;
    const int tx = tid & 15;
    const int ty = tid >> 4;

    const int lrow = tid >> 2;
    const int lk   = (tid & 3) * 4;

    const float* Ag = X  + (size_t)m0 * DIN;
    const float* Bg = Wi + (size_t)n0 * DIN;

    typedef unsigned long long ull;
    union F4U { float4 f; ull u[2]; };

    ull acc2[4][8];   // a-pair (i/2) x j
#pragma unroll
    for (int ip = 0; ip < 4; ip++)
#pragma unroll
        for (int j = 0; j < 8; j++) acc2[ip][j] = 0ull;

    for (int kk = 0; kk < DIN; kk += BK) {
#pragma unroll
        for (int q = 0; q < 2; q++) {
            int r = lrow + 64 * q;
            float4 va = *(const float4*)&Ag[(size_t)r * DIN + kk + lk];
            As[lk + 0][r] = va.x; As[lk + 1][r] = va.y;
            As[lk + 2][r] = va.z; As[lk + 3][r] = va.w;
            float4 vb = *(const float4*)&Bg[(size_t)r * DIN + kk + lk];
            Bs[lk + 0][r] = vb.x; Bs[lk + 1][r] = vb.y;
            Bs[lk + 2][r] = vb.z; Bs[lk + 3][r] = vb.w;
        }
        __syncthreads();

#pragma unroll
        for (int k = 0; k < BK; k++) {
            F4U a0, a1;   // a-pairs come free from the vector load
            a0.f = *(const float4*)&As[k][ty * 8];
            a1.f = *(const float4*)&As[k][ty * 8 + 4];
            ull ap[4] = { a0.u[0], a0.u[1], a1.u[0], a1.u[1] };
            float b[8];
            *(float4*)&b[0] = *(const float4*)&Bs[k][tx * 8];
            *(float4*)&b[4] = *(const float4*)&Bs[k][tx * 8 + 4];
#pragma unroll
            for (int j = 0; j < 8; j++) {
                ull bb = pack_f32x2(b[j], b[j]);
#pragma unroll
                for (int ip = 0; ip < 4; ip++)
                    acc2[ip][j] = fma_f32x2(ap[ip], bb, acc2[ip][j]);
            }
        }
        __syncthreads();
    }

    // epilogue: unpack, add bias, store
#pragma unroll
    for (int ip = 0; ip < 4; ip++) {
        float row0v[8], row1v[8];
#pragma unroll
        for (int j = 0; j < 8; j++) unpack_f32x2(acc2[ip][j], row0v[j], row1v[j]);
        int m_a = m0 + ty * 8 + 2 * ip;
        int m_b = m_a + 1;
#pragma unroll
        for (int j = 0; j < 8; j += 4) {
            int n = n0 + tx * 8 + j;
            float4 v;
            v.x = row0v[j + 0] + bi[n + 0];
            v.y = row0v[j + 1] + bi[n + 1];
            v.z = row0v[j + 2] + bi[n + 2];
            v.w = row0v[j + 3] + bi[n + 3];
            *(float4*)&g_xp[(size_t)m_a * HID + n] = v;
            float4 u;
            u.x = row1v[j + 0] + bi[n + 0];
            u.y = row1v[j + 1] + bi[n + 1];
            u.z = row1v[j + 2] + bi[n + 2];
            u.w = row1v[j + 3] + bi[n + 3];
            *(float4*)&g_xp[(size_t)m_b * HID + n] = u;
        }
    }
}

// ---------------- persistent scan kernel, barrier-free (data-as-flag) ----------------
// R9 structure (best): cooperative spin-gather of h into SMEM + one __syncthreads,
// warp-0 tail, 4-deep sentinel ring. This round: double-pumped poll (2 loads in
// flight -> detect quantum ~ L2lat/2) and even-lane h release BEFORE the v16
// broadcast shfl (release path shortened; out/reset stores after).
__global__ __launch_bounds__(SCAN_TPB, 1) void scan_kernel(
    const float* __restrict__ Wh,
    const float* __restrict__ bh,
    float* __restrict__ out,
    int write_tail)
{
    const int bid  = blockIdx.x;
    const int tid  = threadIdx.x;
    const int w    = tid >> 5;
    const int lane = tid & 31;
    const int kg_lo = lane & 7;
    const int rg    = lane >> 3;
    const int kg    = w * 8 + kg_lo;
    const int row0  = bid * ROWS_PER_CTA + rg * 4;

    typedef unsigned long long ull;
    union Pk { float4 f; uint4 i; ull u[2]; };

    // preload weights, packed as f32x2
    ull Wp[4][8];
#pragma unroll
    for (int r = 0; r < 4; r++)
#pragma unroll
        for (int i = 0; i < 4; i++) {
            Pk v;
            v.f = *(const float4*)&Wh[(size_t)(row0 + r) * HID + kg * 4 + i * 512];
            Wp[r][2 * i]     = v.u[0];
            Wp[r][2 * i + 1] = v.u[1];
        }

    __shared__ uint4 sh_h[HID / 4];           // 8 KB staged hidden state
    __shared__ float red[ROWS_PER_CTA][20];   // stride 20 words: LDS.128-aligned rows

    // warp-0 tail state: lane L handles row L>>1 (duplicated across lane pairs)
    const int trow = lane >> 1;
    const float bhv = bh[bid * ROWS_PER_CTA + trow];
    const float* xp_base = &g_xp[bid * ROWS_PER_CTA + trow];
    float x0 = 0.f, x1 = 0.f, x2 = 0.f, x3 = 0.f;
    if (w == 0) {
        x0 = __ldcs(&xp_base[(size_t)0 * HID]);
        x1 = __ldcs(&xp_base[(size_t)1 * HID]);
        x2 = __ldcs(&xp_base[(size_t)2 * HID]);
        x3 = __ldcs(&xp_base[(size_t)3 * HID]);
    }

    for (int t = 0; t < S_LEN; t++) {
        // Phase A: spin-gather h_t (one float4 per thread) into SMEM.
        // Double-pumped poll: two independent volatile loads in flight; check
        // the older while the newer is airborne -> detect quantum ~ L2lat/2.
        {
            const uint4* hp4 = (const uint4*)g_hr[t & 3] + tid;
            uint4 a = ld_vol4(hp4);
            uint4 b = ld_vol4(hp4);
            while (a.x == SENT || a.y == SENT || a.z == SENT || a.w == SENT) {
                a = b;
                b = ld_vol4(hp4);
            }
            sh_h[tid] = a;
        }
        __syncthreads();

        float xpv = 0.f;
        if (w == 0) {   // rotate xp ring, prefetch t+4
            xpv = x0; x0 = x1; x1 = x2; x2 = x3;
            int tp = t + 4 < S_LEN ? t + 4 : S_LEN - 1;
            x3 = __ldcs(&xp_base[(size_t)tp * HID]);
        }
        // sentinel-reset own rows of the dead slot (h_{t-1}'s slot); safe:
        // gather of h_t complete => all CTAs finished reading h_{t-1}
        if (w == 1 && lane < ROWS_PER_CTA) {
            st_vol_u32((unsigned*)&g_hr[(t + 3) & 3][bid * ROWS_PER_CTA + lane], SENT);
        }

        // Phase B: packed FMA from SMEM h
        Pk h0, h1, h2, h3;
        h0.f = ((const float4*)sh_h)[kg +   0];
        h1.f = ((const float4*)sh_h)[kg + 128];
        h2.f = ((const float4*)sh_h)[kg + 256];
        h3.f = ((const float4*)sh_h)[kg + 384];
        ull hp[8] = { h0.u[0], h0.u[1], h1.u[0], h1.u[1],
                      h2.u[0], h2.u[1], h3.u[0], h3.u[1] };

        ull a2[4] = {0ull, 0ull, 0ull, 0ull};
#pragma unroll
        for (int r = 0; r < 4; r++)
#pragma unroll
            for (int i = 0; i < 8; i++)
                a2[r] = fma_f32x2(Wp[r][i], hp[i], a2[r]);

        float acc[4];
#pragma unroll
        for (int r = 0; r < 4; r++) {
            float lo, hi;
            unpack_f32x2(a2[r], lo, hi);
            acc[r] = lo + hi;
        }

        // reduce across the 8 kg_lo lanes within each rg group
#pragma unroll
        for (int d = 1; d < 8; d <<= 1) {
            acc[0] += __shfl_xor_sync(0xffffffffu, acc[0], d);
            acc[1] += __shfl_xor_sync(0xffffffffu, acc[1], d);
            acc[2] += __shfl_xor_sync(0xffffffffu, acc[2], d);
            acc[3] += __shfl_xor_sync(0xffffffffu, acc[3], d);
        }
        if (kg_lo == 0) {
            red[rg * 4 + 0][w] = acc[0];
            red[rg * 4 + 1][w] = acc[1];
            red[rg * 4 + 2][w] = acc[2];
            red[rg * 4 + 3][w] = acc[3];
        }

        if (w == 0) {
            asm volatile("bar.sync 1, %0;" :: "r"(SCAN_TPB) : "memory");
            // tail: lane L -> row L>>1, half L&1
            const int half = lane & 1;
            float4 p0 = *(const float4*)&red[trow][half * 8];
            float4 p1 = *(const float4*)&red[trow][half * 8 + 4];
            float s = ((p0.x + p0.y) + (p0.z + p0.w))
                    + ((p1.x + p1.y) + (p1.z + p1.w));
            s += __shfl_xor_sync(0xffffffffu, s, 1);   // both lanes of pair: full sum
            float v = tanhf(s + bhv + xpv);
            // RELEASE first: even lane 2L holds row L -> 16x4B, one 64B txn
            if ((lane & 1) == 0) {
                st_vol_f32(&g_hr[(t + 1) & 3][bid * ROWS_PER_CTA + trow], v);
            }
            // off-path: out store (+ final h_n) via broadcast shfl
            float v16 = __shfl_sync(0xffffffffu, v, 2 * (lane & 15));
            if (lane < ROWS_PER_CTA) {
                int j = bid * ROWS_PER_CTA + lane;
                __stcs(&out[(size_t)t * HID + j], v16);
                if (write_tail && t == S_LEN - 1)
                    out[(size_t)S_LEN * HID + j] = v16;  // final hidden state h_n
            }
        } else {
            asm volatile("bar.arrive 1, %0;" :: "r"(SCAN_TPB) : "memory");
        }
        // no grid barrier: next iteration's spin-gather provides the wait
    }
}

// ---------------- launch ----------------
extern "C" void kernel_launch(void* const* d_in, const int* in_sizes, int n_in,
                              void* d_out, int out_size) {
    const float* x  = (const float*)d_in[0];
    const float* Wi = (const float*)d_in[1];
    const float* bi = (const float*)d_in[2];
    const float* Wh = (const float*)d_in[3];
    const float* bh = (const float*)d_in[4];
    float* out = (float*)d_out;

    gemm_xproj<<<dim3(HID / BN, S_LEN / BM), 256>>>(x, Wi, bi);

    int write_tail = (out_size >= S_LEN * HID + HID) ? 1 : 0;
    scan_kernel<<<NCTA, SCAN_TPB>>>(Wh, bh, out, write_tail);
}

// round 12
// speedup vs baseline: 1.1654x; 1.1582x over previous
#include <cuda_runtime.h>
#include <cuda_bf16.h>
#include <cstdint>

#define S_LEN 8192
#define HID   2048
#define DIN   2048

#define NCTA  128
#define ROWS_PER_CTA 16   // 2048 / 128
#define SCAN_TPB 512

#define SENT 0x7fbfffffu   // NaN bit pattern: tanh output can never equal this

// ---------------- device scratch (no allocation allowed) ----------------
// Referenced ONLY from device code (never passed as a kernel arg from host).
__device__ float     g_xp[(size_t)S_LEN * HID];   // 64 MB input projection
__device__ float     g_hr[4][HID];                // 4-deep hidden-state ring

// packed fp32x2 FMA (sm_100+ FFMA2 path — only reachable via PTX)
__device__ __forceinline__ unsigned long long fma_f32x2(
    unsigned long long a, unsigned long long b, unsigned long long c) {
    unsigned long long d;
    asm("fma.rn.f32x2 %0, %1, %2, %3;" : "=l"(d) : "l"(a), "l"(b), "l"(c));
    return d;
}
__device__ __forceinline__ unsigned long long pack_f32x2(float lo, float hi) {
    unsigned long long d;
    asm("mov.b64 %0, {%1, %2};" : "=l"(d) : "f"(lo), "f"(hi));
    return d;
}
__device__ __forceinline__ void unpack_f32x2(unsigned long long v, float& lo, float& hi) {
    asm("mov.b64 {%0, %1}, %2;" : "=f"(lo), "=f"(hi) : "l"(v));
}

__device__ __forceinline__ uint4 ld_vol4(const uint4* p) {
    uint4 v;
    asm volatile("ld.volatile.global.v4.u32 {%0,%1,%2,%3}, [%4];"
                 : "=r"(v.x), "=r"(v.y), "=r"(v.z), "=r"(v.w) : "l"(p) : "memory");
    return v;
}
__device__ __forceinline__ void st_vol_f32(float* p, float v) {
    asm volatile("st.volatile.global.f32 [%0], %1;" :: "l"(p), "f"(v) : "memory");
}
__device__ __forceinline__ void st_vol_u32(unsigned* p, unsigned v) {
    asm volatile("st.volatile.global.u32 [%0], %1;" :: "l"(p), "r"(v) : "memory");
}

// ---------------- x_proj GEMM: g_xp = X @ Wi^T + bi (+ ring init) ----------------
#define BM 128
#define BN 128
#define BK 16

__global__ __launch_bounds__(256, 2) void gemm_xproj(
    const float* __restrict__ X,
    const float* __restrict__ Wi,
    const float* __restrict__ bi)
{
    // block (0,0) resets the h ring: slot 0 = h_0 = 0, slots 1..3 = sentinel.
    // (scan_kernel launches after this kernel completes — stream order.)
    if (blockIdx.x == 0 && blockIdx.y == 0) {
        for (int i = threadIdx.x; i < 4 * HID; i += 256)
            ((unsigned*)g_hr)[i] = (i < HID) ? 0u : SENT;
    }

    __shared__ float As[BK][BM + 4];
    __shared__ float Bs[BK][BN + 4];

    const int m0 = blockIdx.y * BM;
    const int n0 = blockIdx.x * BN;
    const int tid = threadIdx.x;
    const int tx = tid & 15;
    const int ty = tid >> 4;

    const int lrow = tid >> 2;
    const int lk   = (tid & 3) * 4;

    const float* Ag = X  + (size_t)m0 * DIN;
    const float* Bg = Wi + (size_t)n0 * DIN;

    typedef unsigned long long ull;
    union F4U { float4 f; ull u[2]; };

    ull acc2[4][8];   // a-pair (i/2) x j
#pragma unroll
    for (int ip = 0; ip < 4; ip++)
#pragma unroll
        for (int j = 0; j < 8; j++) acc2[ip][j] = 0ull;

    for (int kk = 0; kk < DIN; kk += BK) {
#pragma unroll
        for (int q = 0; q < 2; q++) {
            int r = lrow + 64 * q;
            float4 va = *(const float4*)&Ag[(size_t)r * DIN + kk + lk];
            As[lk + 0][r] = va.x; As[lk + 1][r] = va.y;
            As[lk + 2][r] = va.z; As[lk + 3][r] = va.w;
            float4 vb = *(const float4*)&Bg[(size_t)r * DIN + kk + lk];
            Bs[lk + 0][r] = vb.x; Bs[lk + 1][r] = vb.y;
            Bs[lk + 2][r] = vb.z; Bs[lk + 3][r] = vb.w;
        }
        __syncthreads();

#pragma unroll
        for (int k = 0; k < BK; k++) {
            F4U a0, a1;   // a-pairs come free from the vector load
            a0.f = *(const float4*)&As[k][ty * 8];
            a1.f = *(const float4*)&As[k][ty * 8 + 4];
            ull ap[4] = { a0.u[0], a0.u[1], a1.u[0], a1.u[1] };
            float b[8];
            *(float4*)&b[0] = *(const float4*)&Bs[k][tx * 8];
            *(float4*)&b[4] = *(const float4*)&Bs[k][tx * 8 + 4];
#pragma unroll
            for (int j = 0; j < 8; j++) {
                ull bb = pack_f32x2(b[j], b[j]);
#pragma unroll
                for (int ip = 0; ip < 4; ip++)
                    acc2[ip][j] = fma_f32x2(ap[ip], bb, acc2[ip][j]);
            }
        }
        __syncthreads();
    }

    // epilogue: unpack, add bias, store
#pragma unroll
    for (int ip = 0; ip < 4; ip++) {
        float row0v[8], row1v[8];
#pragma unroll
        for (int j = 0; j < 8; j++) unpack_f32x2(acc2[ip][j], row0v[j], row1v[j]);
        int m_a = m0 + ty * 8 + 2 * ip;
        int m_b = m_a + 1;
#pragma unroll
        for (int j = 0; j < 8; j += 4) {
            int n = n0 + tx * 8 + j;
            float4 v;
            v.x = row0v[j + 0] + bi[n + 0];
            v.y = row0v[j + 1] + bi[n + 1];
            v.z = row0v[j + 2] + bi[n + 2];
            v.w = row0v[j + 3] + bi[n + 3];
            *(float4*)&g_xp[(size_t)m_a * HID + n] = v;
            float4 u;
            u.x = row1v[j + 0] + bi[n + 0];
            u.y = row1v[j + 1] + bi[n + 1];
            u.z = row1v[j + 2] + bi[n + 2];
            u.w = row1v[j + 3] + bi[n + 3];
            *(float4*)&g_xp[(size_t)m_b * HID + n] = u;
        }
    }
}

// ---------------- persistent scan kernel, barrier-free (data-as-flag) ----------------
// R9 structure (proven best): cooperative single-pump spin-gather of h into SMEM
// + one __syncthreads, warp-0 tail, 4-deep sentinel ring.
// This round's single delta: after s += shfl_xor(s,1), BOTH lanes of each pair
// hold the full row sum, so even lanes store the g_hr release directly and odd
// lanes store out[t] — no v16 broadcast shfl, out-store off the release path.
__global__ __launch_bounds__(SCAN_TPB, 1) void scan_kernel(
    const float* __restrict__ Wh,
    const float* __restrict__ bh,
    float* __restrict__ out,
    int write_tail)
{
    const int bid  = blockIdx.x;
    const int tid  = threadIdx.x;
    const int w    = tid >> 5;
    const int lane = tid & 31;
    const int kg_lo = lane & 7;
    const int rg    = lane >> 3;
    const int kg    = w * 8 + kg_lo;
    const int row0  = bid * ROWS_PER_CTA + rg * 4;

    typedef unsigned long long ull;
    union Pk { float4 f; uint4 i; ull u[2]; };

    // preload weights, packed as f32x2
    ull Wp[4][8];
#pragma unroll
    for (int r = 0; r < 4; r++)
#pragma unroll
        for (int i = 0; i < 4; i++) {
            Pk v;
            v.f = *(const float4*)&Wh[(size_t)(row0 + r) * HID + kg * 4 + i * 512];
            Wp[r][2 * i]     = v.u[0];
            Wp[r][2 * i + 1] = v.u[1];
        }

    __shared__ uint4 sh_h[HID / 4];           // 8 KB staged hidden state
    __shared__ float red[ROWS_PER_CTA][20];   // stride 20 words: LDS.128-aligned rows

    // warp-0 tail state: lane L handles row L>>1 (duplicated across lane pairs)
    const int trow = lane >> 1;
    const float bhv = bh[bid * ROWS_PER_CTA + trow];
    const float* xp_base = &g_xp[bid * ROWS_PER_CTA + trow];
    float x0 = 0.f, x1 = 0.f, x2 = 0.f, x3 = 0.f;
    if (w == 0) {
        x0 = __ldcs(&xp_base[(size_t)0 * HID]);
        x1 = __ldcs(&xp_base[(size_t)1 * HID]);
        x2 = __ldcs(&xp_base[(size_t)2 * HID]);
        x3 = __ldcs(&xp_base[(size_t)3 * HID]);
    }

    for (int t = 0; t < S_LEN; t++) {
        // Phase A: spin-gather h_t (one float4 per thread) into SMEM.
        // Single-pump poll (R9): lowest L2 poll traffic; per-word sentinel
        // checks make torn vector loads benign.
        {
            const uint4* hp4 = (const uint4*)g_hr[t & 3] + tid;
            uint4 hv;
            do {
                hv = ld_vol4(hp4);
            } while (hv.x == SENT || hv.y == SENT || hv.z == SENT || hv.w == SENT);
            sh_h[tid] = hv;
        }
        __syncthreads();

        float xpv = 0.f;
        if (w == 0) {   // rotate xp ring, prefetch t+4
            xpv = x0; x0 = x1; x1 = x2; x2 = x3;
            int tp = t + 4 < S_LEN ? t + 4 : S_LEN - 1;
            x3 = __ldcs(&xp_base[(size_t)tp * HID]);
        }
        // sentinel-reset own rows of the dead slot (h_{t-1}'s slot); safe:
        // gather of h_t complete => all CTAs finished reading h_{t-1}
        if (w == 1 && lane < ROWS_PER_CTA) {
            st_vol_u32((unsigned*)&g_hr[(t + 3) & 3][bid * ROWS_PER_CTA + lane], SENT);
        }

        // Phase B: packed FMA from SMEM h
        Pk h0, h1, h2, h3;
        h0.f = ((const float4*)sh_h)[kg +   0];
        h1.f = ((const float4*)sh_h)[kg + 128];
        h2.f = ((const float4*)sh_h)[kg + 256];
        h3.f = ((const float4*)sh_h)[kg + 384];
        ull hp[8] = { h0.u[0], h0.u[1], h1.u[0], h1.u[1],
                      h2.u[0], h2.u[1], h3.u[0], h3.u[1] };

        ull a2[4] = {0ull, 0ull, 0ull, 0ull};
#pragma unroll
        for (int r = 0; r < 4; r++)
#pragma unroll
            for (int i = 0; i < 8; i++)
                a2[r] = fma_f32x2(Wp[r][i], hp[i], a2[r]);

        float acc[4];
#pragma unroll
        for (int r = 0; r < 4; r++) {
            float lo, hi;
            unpack_f32x2(a2[r], lo, hi);
            acc[r] = lo + hi;
        }

        // reduce across the 8 kg_lo lanes within each rg group
#pragma unroll
        for (int d = 1; d < 8; d <<= 1) {
            acc[0] += __shfl_xor_sync(0xffffffffu, acc[0], d);
            acc[1] += __shfl_xor_sync(0xffffffffu, acc[1], d);
            acc[2] += __shfl_xor_sync(0xffffffffu, acc[2], d);
            acc[3] += __shfl_xor_sync(0xffffffffu, acc[3], d);
        }
        if (kg_lo == 0) {
            red[rg * 4 + 0][w] = acc[0];
            red[rg * 4 + 1][w] = acc[1];
            red[rg * 4 + 2][w] = acc[2];
            red[rg * 4 + 3][w] = acc[3];
        }

        if (w == 0) {
            asm volatile("bar.sync 1, %0;" :: "r"(SCAN_TPB) : "memory");
            // tail: lane pair (2L, 2L+1) -> row L; lane half L&1
            const int half = lane & 1;
            float4 p0 = *(const float4*)&red[trow][half * 8];
            float4 p1 = *(const float4*)&red[trow][half * 8 + 4];
            float s = ((p0.x + p0.y) + (p0.z + p0.w))
                    + ((p1.x + p1.y) + (p1.z + p1.w));
            s += __shfl_xor_sync(0xffffffffu, s, 1);   // both lanes: full row sum
            float v = tanhf(s + bhv + xpv);
            int j = bid * ROWS_PER_CTA + trow;
            if (half == 0) {
                // RELEASE: even lanes store h -> 16x4B consecutive, one 64B txn
                st_vol_f32(&g_hr[(t + 1) & 3][j], v);
            } else {
                // off the release path: odd lanes store out[t] (+ h_n at the end)
                __stcs(&out[(size_t)t * HID + j], v);
                if (write_tail && t == S_LEN - 1)
                    out[(size_t)S_LEN * HID + j] = v;   // final hidden state h_n
            }
        } else {
            asm volatile("bar.arrive 1, %0;" :: "r"(SCAN_TPB) : "memory");
        }
        // no grid barrier: next iteration's spin-gather provides the wait
    }
}

// ---------------- launch ----------------
extern "C" void kernel_launch(void* const* d_in, const int* in_sizes, int n_in,
                              void* d_out, int out_size) {
    const float* x  = (const float*)d_in[0];
    const float* Wi = (const float*)d_in[1];
    const float* bi = (const float*)d_in[2];
    const float* Wh = (const float*)d_in[3];
    const float* bh = (const float*)d_in[4];
    float* out = (float*)d_out;

    gemm_xproj<<<dim3(HID / BN, S_LEN / BM), 256>>>(x, Wi, bi);

    int write_tail = (out_size >= S_LEN * HID + HID) ? 1 : 0;
    scan_kernel<<<NCTA, SCAN_TPB>>>(Wh, bh, out, write_tail);
}